// round 7
// baseline (speedup 1.0000x reference)
#include <cuda_runtime.h>
#include <cuda_bf16.h>

#define N_NODES 50000
#define N_EDGES_MAX 600000
#define D 128
#define N_CLASSES 40

#define SCAN_BLK 1024
#define SCAN_NBLK ((N_NODES + SCAN_BLK - 1) / SCAN_BLK)   // 49

// Scratch (static device globals — no allocations allowed).
// Only dereferenced from DEVICE code (host shadow deref is silent on GB300/ATS);
// host side only takes the address via cudaGetSymbolAddress for memset.
__device__ float g_acc[N_NODES * D];   // gather output / GEMM input
__device__ float g_buf0[N_NODES * D];  // layer activations ping
__device__ float g_buf1[N_NODES * D];  // layer activations pong
__device__ int   g_cnt[N_NODES];       // in-degree histogram
__device__ int   g_row[N_NODES + 1];   // CSR row pointers (by dst)
__device__ int   g_cur[N_NODES];       // fill cursors
__device__ int   g_esrc[N_EDGES_MAX];  // CSR column indices (src nodes)
__device__ int   g_bsum[SCAN_NBLK];    // per-block scan totals

// ---------------------------------------------------------------------------
// CSR build
// ---------------------------------------------------------------------------
__global__ void gcn_hist_kernel(const int* __restrict__ dst, int n_edges) {
    int e = blockIdx.x * blockDim.x + threadIdx.x;
    if (e < n_edges) atomicAdd(&g_cnt[dst[e]], 1);
}

__global__ void gcn_scanA_kernel() {
    __shared__ int sh[SCAN_BLK];
    int t = threadIdx.x;
    int idx = blockIdx.x * SCAN_BLK + t;
    int v = (idx < N_NODES) ? g_cnt[idx] : 0;
    sh[t] = v;
    __syncthreads();
    for (int off = 1; off < SCAN_BLK; off <<= 1) {
        int u = (t >= off) ? sh[t - off] : 0;
        __syncthreads();
        sh[t] += u;
        __syncthreads();
    }
    if (idx < N_NODES) g_row[idx] = sh[t] - v;
    if (t == SCAN_BLK - 1) g_bsum[blockIdx.x] = sh[t];
}

// Pass B: block offset = prefix of g_bsum, staged through smem (no serial L2 chain).
__global__ void gcn_scanB_kernel() {
    __shared__ int sh[64];
    __shared__ int s_off;
    int t = threadIdx.x;
    int blk = blockIdx.x;
    if (t < 64) sh[t] = (t < SCAN_NBLK) ? g_bsum[t] : 0;
    __syncthreads();
    if (t == 0) {
        int o = 0;
#pragma unroll 7
        for (int b = 0; b < blk; b++) o += sh[b];
        s_off = o;
    }
    __syncthreads();
    int off = s_off;
    int idx = blk * SCAN_BLK + t;
    if (idx < N_NODES) {
        int r = g_row[idx] + off;
        g_row[idx] = r;
        g_cur[idx] = r;
        if (idx == N_NODES - 1) g_row[N_NODES] = r + g_cnt[idx];
    }
}

__global__ void gcn_fill_kernel(const int* __restrict__ src,
                                const int* __restrict__ dst, int n_edges) {
    int e = blockIdx.x * blockDim.x + threadIdx.x;
    if (e < n_edges) {
        int pos = atomicAdd(&g_cur[dst[e]], 1);
        g_esrc[pos] = src[e];
    }
}

// ---------------------------------------------------------------------------
// Buffer selection by template (device-symbol addresses stay device-side).
// SEL: 0 = param pointer, 1 = g_buf0, 2 = g_buf1
// ---------------------------------------------------------------------------
template <int SEL>
__device__ __forceinline__ const float* sel_in(const float* p) {
    if (SEL == 0) return p;
    if (SEL == 1) return g_buf0;
    return g_buf1;
}
template <int SEL>
__device__ __forceinline__ float* sel_out(float* p) {
    if (SEL == 0) return p;
    if (SEL == 1) return g_buf0;
    return g_buf1;
}

// ---------------------------------------------------------------------------
// Gather: one warp per node. g_acc[n] = in[n] + sum_{s in nbrs(n)} in[s].
// High occupancy (no big smem) to hide L2-hit latency.
// ---------------------------------------------------------------------------
template <int INSEL>
__global__ void gcn_gather_kernel(const float* __restrict__ in_p) {
    const float* in = sel_in<INSEL>(in_p);
    int node = blockIdx.x * (blockDim.x >> 5) + (threadIdx.x >> 5);
    if (node >= N_NODES) return;
    int lane = threadIdx.x & 31;
    int beg = g_row[node];
    int end = g_row[node + 1];
    float4 acc = *(const float4*)(in + (size_t)node * D + lane * 4);  // self
    int i = beg;
    for (; i + 4 <= end; i += 4) {
        int s0 = g_esrc[i], s1 = g_esrc[i + 1], s2 = g_esrc[i + 2], s3 = g_esrc[i + 3];
        float4 v0 = *(const float4*)(in + (size_t)s0 * D + lane * 4);
        float4 v1 = *(const float4*)(in + (size_t)s1 * D + lane * 4);
        float4 v2 = *(const float4*)(in + (size_t)s2 * D + lane * 4);
        float4 v3 = *(const float4*)(in + (size_t)s3 * D + lane * 4);
        acc.x += v0.x + v1.x + v2.x + v3.x;
        acc.y += v0.y + v1.y + v2.y + v3.y;
        acc.z += v0.z + v1.z + v2.z + v3.z;
        acc.w += v0.w + v1.w + v2.w + v3.w;
    }
    for (; i < end; i++) {
        int s = g_esrc[i];
        float4 v = *(const float4*)(in + (size_t)s * D + lane * 4);
        acc.x += v.x; acc.y += v.y; acc.z += v.z; acc.w += v.w;
    }
    *(float4*)(g_acc + (size_t)node * D + lane * 4) = acc;
}

// ---------------------------------------------------------------------------
// FFMA2 GEMM with pre-duplicated A tile:
//   As2[r][2k], As2[r][2k+1] both hold g_acc[row0+r][k], so the a-operand of
//   fma.rn.f32x2 is a single broadcast LDS.64 — no mov-pack in the hot loop.
//   Per k per thread: 4 LDS.64 (a) + TNP LDS.64 (b) + 4*TNP FFMA2.
// ---------------------------------------------------------------------------
template <int OUTSEL, int BN, int TNP, bool RELU>
__global__ __launch_bounds__(256)
void gcn_gemm_kernel(const float* __restrict__ W,
                     const float* __restrict__ bias,
                     float* __restrict__ out_p,
                     int n_out, int ldo) {
    constexpr int BM = 64;
    constexpr int K = D;
    constexpr int LDA2 = 2 * K + 8;   // 264 floats (1056B row stride, 16B aligned)
    constexpr int LDB = BN + 8;       // even pad for 8B pair loads
    extern __shared__ float sm[];
    float* As2 = sm;                  // [BM][LDA2]  duplicated pairs
    float* Bs  = sm + BM * LDA2;      // [K][LDB]

    int tid = threadIdx.x;
    int row0 = blockIdx.x * BM;

    // W -> Bs (transposed)
    for (int i = tid; i < BN * K; i += 256) {
        int j = i / K, k = i % K;
        float v = (j < n_out) ? __ldg(W + j * K + k) : 0.f;
        Bs[k * LDB + j] = v;
    }
    // g_acc -> As2, duplicating each value into an adjacent pair
    for (int i = tid * 4; i < BM * K; i += 256 * 4) {
        int r = i / K, k = i % K;
        int g = row0 + r;
        float4 v = (g < N_NODES) ? *(const float4*)(g_acc + (size_t)g * K + k)
                                 : make_float4(0.f, 0.f, 0.f, 0.f);
        float4 d0 = make_float4(v.x, v.x, v.y, v.y);
        float4 d1 = make_float4(v.z, v.z, v.w, v.w);
        *(float4*)(As2 + r * LDA2 + 2 * k) = d0;
        *(float4*)(As2 + r * LDA2 + 2 * k + 4) = d1;
    }
    __syncthreads();

    int tc = tid & 15;
    int tr = tid >> 4;

    unsigned long long acc[4][TNP];
#pragma unroll
    for (int ii = 0; ii < 4; ii++)
#pragma unroll
        for (int jj = 0; jj < TNP; jj++) acc[ii][jj] = 0ULL;

#pragma unroll 4
    for (int k = 0; k < K; k++) {
        unsigned long long ap[4], bp[TNP];
#pragma unroll
        for (int ii = 0; ii < 4; ii++)
            ap[ii] = *(const unsigned long long*)(As2 + (tr * 4 + ii) * LDA2 + 2 * k);
#pragma unroll
        for (int jj = 0; jj < TNP; jj++)
            bp[jj] = *(const unsigned long long*)(Bs + k * LDB + 2 * tc + 32 * jj);
#pragma unroll
        for (int ii = 0; ii < 4; ii++)
#pragma unroll
            for (int jj = 0; jj < TNP; jj++)
                asm("fma.rn.f32x2 %0, %1, %2, %0;"
                    : "+l"(acc[ii][jj]) : "l"(ap[ii]), "l"(bp[jj]));
    }

    float* outp = sel_out<OUTSEL>(out_p);
#pragma unroll
    for (int ii = 0; ii < 4; ii++) {
        int g = row0 + tr * 4 + ii;
        if (g >= N_NODES) continue;
#pragma unroll
        for (int jj = 0; jj < TNP; jj++) {
            int j0 = 2 * tc + 32 * jj;
            float lo, hi;
            asm("mov.b64 {%0, %1}, %2;" : "=f"(lo), "=f"(hi) : "l"(acc[ii][jj]));
            if (j0 < n_out) {
                float v = lo + __ldg(bias + j0);
                if (RELU) v = fmaxf(v, 0.f);
                outp[(size_t)g * ldo + j0] = v;
            }
            if (j0 + 1 < n_out) {
                float v = hi + __ldg(bias + j0 + 1);
                if (RELU) v = fmaxf(v, 0.f);
                outp[(size_t)g * ldo + j0 + 1] = v;
            }
        }
    }
}

// ---------------------------------------------------------------------------
extern "C" void kernel_launch(void* const* d_in, const int* in_sizes, int n_in,
                              void* d_out, int out_size) {
    const float* x  = (const float*)d_in[0];
    const int* src  = (const int*)d_in[1];
    const int* dst  = (const int*)d_in[2];
    const float* W0 = (const float*)d_in[3];
    const float* b0 = (const float*)d_in[4];
    const float* W1 = (const float*)d_in[5];
    const float* b1 = (const float*)d_in[6];
    const float* W2 = (const float*)d_in[7];
    const float* b2 = (const float*)d_in[8];
    float* out = (float*)d_out;
    int n_edges = in_sizes[1];

    constexpr int SMEM_BIG   = (64 * 264 + 128 * 136) * 4;  // 137216 B
    constexpr int SMEM_SMALL = (64 * 264 + 128 * 72) * 4;   // 104448 B
    static bool attr_done = false;
    if (!attr_done) {
        cudaFuncSetAttribute(gcn_gemm_kernel<1, 128, 4, true>,
                             cudaFuncAttributeMaxDynamicSharedMemorySize, SMEM_BIG);
        cudaFuncSetAttribute(gcn_gemm_kernel<2, 128, 4, true>,
                             cudaFuncAttributeMaxDynamicSharedMemorySize, SMEM_BIG);
        cudaFuncSetAttribute(gcn_gemm_kernel<0, 64, 2, false>,
                             cudaFuncAttributeMaxDynamicSharedMemorySize, SMEM_SMALL);
        attr_done = true;
    }

    // Zero the histogram with a capturable async memset (symbol address via API).
    void* cnt_ptr = nullptr;
    cudaGetSymbolAddress(&cnt_ptr, g_cnt);
    cudaMemsetAsync(cnt_ptr, 0, N_NODES * sizeof(int));

    int edge_blocks = (n_edges + 255) / 256;
    int gath_blocks = (N_NODES + 7) / 8;
    int gemm_blocks = (N_NODES + 63) / 64;

    // CSR build
    gcn_hist_kernel<<<edge_blocks, 256>>>(dst, n_edges);
    gcn_scanA_kernel<<<SCAN_NBLK, SCAN_BLK>>>();
    gcn_scanB_kernel<<<SCAN_NBLK, SCAN_BLK>>>();
    gcn_fill_kernel<<<edge_blocks, 256>>>(src, dst, n_edges);

    // Layer 0: x --gather--> g_acc --gemm--> g_buf0
    gcn_gather_kernel<0><<<gath_blocks, 256>>>(x);
    gcn_gemm_kernel<1, 128, 4, true><<<gemm_blocks, 256, SMEM_BIG>>>(
        W0, b0, nullptr, D, D);
    // Layer 1: g_buf0 --gather--> g_acc --gemm--> g_buf1
    gcn_gather_kernel<1><<<gath_blocks, 256>>>(nullptr);
    gcn_gemm_kernel<2, 128, 4, true><<<gemm_blocks, 256, SMEM_BIG>>>(
        W1, b1, nullptr, D, D);
    // Layer 2 (head): g_buf1 --gather--> g_acc --gemm--> out
    gcn_gather_kernel<2><<<gath_blocks, 256>>>(nullptr);
    gcn_gemm_kernel<0, 64, 2, false><<<gemm_blocks, 256, SMEM_SMALL>>>(
        W2, b2, out, N_CLASSES, N_CLASSES);
}

// round 8
// speedup vs baseline: 1.2495x; 1.2495x over previous
#include <cuda_runtime.h>
#include <cuda_bf16.h>

#define N_NODES 50000
#define N_EDGES_MAX 600000
#define D 128
#define N_CLASSES 40

#define SCAN_BLK 1024
#define SCAN_NBLK ((N_NODES + SCAN_BLK - 1) / SCAN_BLK)   // 49

// Scratch (static device globals — no allocations allowed).
// Only dereferenced from DEVICE code (host shadow deref is silent on GB300/ATS);
// host side only takes addresses via cudaGetSymbolAddress for memset.
__device__ float g_acc[N_NODES * D];   // gather output / GEMM input
__device__ float g_buf0[N_NODES * D];  // layer activations ping
__device__ float g_buf1[N_NODES * D];  // layer activations pong
__device__ int   g_cnt[N_NODES];       // in-degree histogram
__device__ int   g_row[N_NODES + 1];   // CSR row pointers (by dst)
__device__ int   g_cur[N_NODES];       // fill cursors
__device__ int   g_esrc[N_EDGES_MAX];  // CSR column indices (src nodes)
__device__ int   g_bsum[SCAN_NBLK];    // per-block scan totals

// ---------------------------------------------------------------------------
// CSR build
// ---------------------------------------------------------------------------
__global__ void gcn_hist_kernel(const int* __restrict__ dst, int n_edges) {
    int e = blockIdx.x * blockDim.x + threadIdx.x;
    if (e < n_edges) atomicAdd(&g_cnt[dst[e]], 1);
}

__global__ void gcn_scanA_kernel() {
    __shared__ int sh[SCAN_BLK];
    int t = threadIdx.x;
    int idx = blockIdx.x * SCAN_BLK + t;
    int v = (idx < N_NODES) ? g_cnt[idx] : 0;
    sh[t] = v;
    __syncthreads();
    for (int off = 1; off < SCAN_BLK; off <<= 1) {
        int u = (t >= off) ? sh[t - off] : 0;
        __syncthreads();
        sh[t] += u;
        __syncthreads();
    }
    if (idx < N_NODES) g_row[idx] = sh[t] - v;
    if (t == SCAN_BLK - 1) g_bsum[blockIdx.x] = sh[t];
}

// Pass B: block offset = prefix of g_bsum staged through smem (no serial L2 chain).
__global__ void gcn_scanB_kernel() {
    __shared__ int sh[64];
    __shared__ int s_off;
    int t = threadIdx.x;
    int blk = blockIdx.x;
    if (t < 64) sh[t] = (t < SCAN_NBLK) ? g_bsum[t] : 0;
    __syncthreads();
    if (t == 0) {
        int o = 0;
#pragma unroll 7
        for (int b = 0; b < blk; b++) o += sh[b];
        s_off = o;
    }
    __syncthreads();
    int off = s_off;
    int idx = blk * SCAN_BLK + t;
    if (idx < N_NODES) {
        int r = g_row[idx] + off;
        g_row[idx] = r;
        g_cur[idx] = r;
        if (idx == N_NODES - 1) g_row[N_NODES] = r + g_cnt[idx];
    }
}

__global__ void gcn_fill_kernel(const int* __restrict__ src,
                                const int* __restrict__ dst, int n_edges) {
    int e = blockIdx.x * blockDim.x + threadIdx.x;
    if (e < n_edges) {
        int pos = atomicAdd(&g_cur[dst[e]], 1);
        g_esrc[pos] = src[e];
    }
}

// ---------------------------------------------------------------------------
// Buffer selection by template (device-symbol addresses stay device-side).
// SEL: 0 = param pointer, 1 = g_buf0, 2 = g_buf1
// ---------------------------------------------------------------------------
template <int SEL>
__device__ __forceinline__ const float* sel_in(const float* p) {
    if (SEL == 0) return p;
    if (SEL == 1) return g_buf0;
    return g_buf1;
}
template <int SEL>
__device__ __forceinline__ float* sel_out(float* p) {
    if (SEL == 0) return p;
    if (SEL == 1) return g_buf0;
    return g_buf1;
}

// ---------------------------------------------------------------------------
// Gather: one warp per node. g_acc[n] = in[n] + sum_{s in nbrs(n)} in[s].
// No smem — high occupancy hides L2-hit latency.
// ---------------------------------------------------------------------------
template <int INSEL>
__global__ void gcn_gather_kernel(const float* __restrict__ in_p) {
    const float* in = sel_in<INSEL>(in_p);
    int node = blockIdx.x * (blockDim.x >> 5) + (threadIdx.x >> 5);
    if (node >= N_NODES) return;
    int lane = threadIdx.x & 31;
    int beg = g_row[node];
    int end = g_row[node + 1];
    float4 acc = *(const float4*)(in + (size_t)node * D + lane * 4);  // self
    int i = beg;
    for (; i + 4 <= end; i += 4) {
        int s0 = g_esrc[i], s1 = g_esrc[i + 1], s2 = g_esrc[i + 2], s3 = g_esrc[i + 3];
        float4 v0 = *(const float4*)(in + (size_t)s0 * D + lane * 4);
        float4 v1 = *(const float4*)(in + (size_t)s1 * D + lane * 4);
        float4 v2 = *(const float4*)(in + (size_t)s2 * D + lane * 4);
        float4 v3 = *(const float4*)(in + (size_t)s3 * D + lane * 4);
        acc.x += v0.x + v1.x + v2.x + v3.x;
        acc.y += v0.y + v1.y + v2.y + v3.y;
        acc.z += v0.z + v1.z + v2.z + v3.z;
        acc.w += v0.w + v1.w + v2.w + v3.w;
    }
    for (; i < end; i++) {
        int s = g_esrc[i];
        float4 v = *(const float4*)(in + (size_t)s * D + lane * 4);
        acc.x += v.x; acc.y += v.y; acc.z += v.z; acc.w += v.w;
    }
    *(float4*)(g_acc + (size_t)node * D + lane * 4) = acc;
}

// ---------------------------------------------------------------------------
// FFMA2 GEMM (R5 layout — 103 KB smem keeps 2 CTAs/SM, which measured faster
// than any lower-occupancy variant with fewer issue slots):
//   res[n, j] = act( sum_k g_acc[n,k] * W[j,k] + bias[j] )
// Each thread: 4 rows x TNP column-pairs, fma.rn.f32x2 on packed pairs.
// ---------------------------------------------------------------------------
template <int OUTSEL, int BN, int TNP, bool RELU>
__global__ __launch_bounds__(256)
void gcn_gemm_kernel(const float* __restrict__ W,
                     const float* __restrict__ bias,
                     float* __restrict__ out_p,
                     int n_out, int ldo) {
    constexpr int BM = 64;
    constexpr int K = D;
    constexpr int LDA = K + 4;    // 132
    constexpr int LDB = BN + 8;   // even pad, 8B-aligned pair loads
    extern __shared__ float sm[];
    float* As = sm;               // [BM][LDA]
    float* Bs = sm + BM * LDA;    // [K][LDB]

    int tid = threadIdx.x;
    int row0 = blockIdx.x * BM;

    for (int i = tid; i < BN * K; i += 256) {
        int j = i / K, k = i % K;
        float v = (j < n_out) ? __ldg(W + j * K + k) : 0.f;
        Bs[k * LDB + j] = v;
    }
    for (int i = tid * 4; i < BM * K; i += 256 * 4) {
        int r = i / K, k = i % K;
        int g = row0 + r;
        float4 v = (g < N_NODES) ? *(const float4*)(g_acc + (size_t)g * K + k)
                                 : make_float4(0.f, 0.f, 0.f, 0.f);
        *(float4*)(As + r * LDA + k) = v;
    }
    __syncthreads();

    int tc = tid & 15;
    int tr = tid >> 4;

    unsigned long long acc[4][TNP];
#pragma unroll
    for (int ii = 0; ii < 4; ii++)
#pragma unroll
        for (int jj = 0; jj < TNP; jj++) acc[ii][jj] = 0ULL;

#pragma unroll 4
    for (int k = 0; k < K; k++) {
        unsigned long long ap[4], bp[TNP];
#pragma unroll
        for (int ii = 0; ii < 4; ii++) {
            float a = As[(tr * 4 + ii) * LDA + k];
            asm("mov.b64 %0, {%1, %2};" : "=l"(ap[ii]) : "f"(a), "f"(a));
        }
#pragma unroll
        for (int jj = 0; jj < TNP; jj++)
            bp[jj] = *(const unsigned long long*)(Bs + k * LDB + 2 * tc + 32 * jj);
#pragma unroll
        for (int ii = 0; ii < 4; ii++)
#pragma unroll
            for (int jj = 0; jj < TNP; jj++)
                asm("fma.rn.f32x2 %0, %1, %2, %0;"
                    : "+l"(acc[ii][jj]) : "l"(ap[ii]), "l"(bp[jj]));
    }

    float* outp = sel_out<OUTSEL>(out_p);
#pragma unroll
    for (int ii = 0; ii < 4; ii++) {
        int g = row0 + tr * 4 + ii;
        if (g >= N_NODES) continue;
#pragma unroll
        for (int jj = 0; jj < TNP; jj++) {
            int j0 = 2 * tc + 32 * jj;
            float lo, hi;
            asm("mov.b64 {%0, %1}, %2;" : "=f"(lo), "=f"(hi) : "l"(acc[ii][jj]));
            if (j0 < n_out) {
                float v = lo + __ldg(bias + j0);
                if (RELU) v = fmaxf(v, 0.f);
                outp[(size_t)g * ldo + j0] = v;
            }
            if (j0 + 1 < n_out) {
                float v = hi + __ldg(bias + j0 + 1);
                if (RELU) v = fmaxf(v, 0.f);
                outp[(size_t)g * ldo + j0 + 1] = v;
            }
        }
    }
}

// ---------------------------------------------------------------------------
extern "C" void kernel_launch(void* const* d_in, const int* in_sizes, int n_in,
                              void* d_out, int out_size) {
    const float* x  = (const float*)d_in[0];
    const int* src  = (const int*)d_in[1];
    const int* dst  = (const int*)d_in[2];
    const float* W0 = (const float*)d_in[3];
    const float* b0 = (const float*)d_in[4];
    const float* W1 = (const float*)d_in[5];
    const float* b1 = (const float*)d_in[6];
    const float* W2 = (const float*)d_in[7];
    const float* b2 = (const float*)d_in[8];
    float* out = (float*)d_out;
    int n_edges = in_sizes[1];

    constexpr int SMEM_BIG   = (64 * 132 + 128 * 136) * 4;  // 103424 B -> 2 CTA/SM
    constexpr int SMEM_SMALL = (64 * 132 + 128 * 72) * 4;   //  70656 B
    static bool attr_done = false;
    if (!attr_done) {
        cudaFuncSetAttribute(gcn_gemm_kernel<1, 128, 4, true>,
                             cudaFuncAttributeMaxDynamicSharedMemorySize, SMEM_BIG);
        cudaFuncSetAttribute(gcn_gemm_kernel<2, 128, 4, true>,
                             cudaFuncAttributeMaxDynamicSharedMemorySize, SMEM_BIG);
        cudaFuncSetAttribute(gcn_gemm_kernel<0, 64, 2, false>,
                             cudaFuncAttributeMaxDynamicSharedMemorySize, SMEM_SMALL);
        attr_done = true;
    }

    // Zero the histogram with a capturable async memset (symbol address via API).
    void* cnt_ptr = nullptr;
    cudaGetSymbolAddress(&cnt_ptr, g_cnt);
    cudaMemsetAsync(cnt_ptr, 0, N_NODES * sizeof(int));

    int edge_blocks = (n_edges + 255) / 256;
    int gath_blocks = (N_NODES + 7) / 8;
    int gemm_blocks = (N_NODES + 63) / 64;

    // CSR build
    gcn_hist_kernel<<<edge_blocks, 256>>>(dst, n_edges);
    gcn_scanA_kernel<<<SCAN_NBLK, SCAN_BLK>>>();
    gcn_scanB_kernel<<<SCAN_NBLK, SCAN_BLK>>>();
    gcn_fill_kernel<<<edge_blocks, 256>>>(src, dst, n_edges);

    // Layer 0: x --gather--> g_acc --gemm--> g_buf0
    gcn_gather_kernel<0><<<gath_blocks, 256>>>(x);
    gcn_gemm_kernel<1, 128, 4, true><<<gemm_blocks, 256, SMEM_BIG>>>(
        W0, b0, nullptr, D, D);
    // Layer 1: g_buf0 --gather--> g_acc --gemm--> g_buf1
    gcn_gather_kernel<1><<<gath_blocks, 256>>>(nullptr);
    gcn_gemm_kernel<2, 128, 4, true><<<gemm_blocks, 256, SMEM_BIG>>>(
        W1, b1, nullptr, D, D);
    // Layer 2 (head): g_buf1 --gather--> g_acc --gemm--> out
    gcn_gather_kernel<2><<<gath_blocks, 256>>>(nullptr);
    gcn_gemm_kernel<0, 64, 2, false><<<gemm_blocks, 256, SMEM_SMALL>>>(
        W2, b2, out, N_CLASSES, N_CLASSES);
}